// round 16
// baseline (speedup 1.0000x reference)
#include <cuda_runtime.h>
#include <cuda_bf16.h>
#include <math.h>
#include <stdint.h>

// ---------------- problem constants ----------------
#define Bq   16
#define LQ   1024
#define Dm   256
#define Hh   8
#define Ll   4
#define Pp   4
#define DFF  1024
#define DH   32
#define LV   5440
#define M1   (Bq*LQ)       // 16384
#define MV   (Bq*LV)       // 87040
#define EPSV 1e-5f

typedef unsigned long long u64;
typedef uint32_t u32;

// ---------------- f32x2 helpers (attention) ----------------
__device__ __forceinline__ u64 pack2(float x, float y) {
    u64 r; asm("mov.b64 %0, {%1, %2};" : "=l"(r) : "f"(x), "f"(y)); return r;
}
__device__ __forceinline__ float2 unpack2(u64 v) {
    float2 f; asm("mov.b64 {%0, %1}, %2;" : "=f"(f.x), "=f"(f.y) : "l"(v)); return f;
}
__device__ __forceinline__ void ffma2(u64& d, u64 a, u64 b) {
    asm("fma.rn.f32x2 %0, %1, %2, %0;" : "+l"(d) : "l"(a), "l"(b));
}
__device__ __forceinline__ void fmul2(u64& d, u64 a) {
    asm("mul.rn.f32x2 %0, %0, %1;" : "+l"(d) : "l"(a));
}

// ---------------- HMMA + cp.async + ldmatrix helpers ----------------
__device__ __forceinline__ void mma16816(float* c, const u32* a, const u32* b) {
    asm volatile(
        "mma.sync.aligned.m16n8k16.row.col.f32.bf16.bf16.f32 "
        "{%0,%1,%2,%3}, {%4,%5,%6,%7}, {%8,%9}, {%0,%1,%2,%3};"
        : "+f"(c[0]), "+f"(c[1]), "+f"(c[2]), "+f"(c[3])
        : "r"(a[0]), "r"(a[1]), "r"(a[2]), "r"(a[3]), "r"(b[0]), "r"(b[1]));
}
__device__ __forceinline__ u32 smem_u32(const void* p) {
    u32 a;
    asm("{ .reg .u64 t; cvta.to.shared.u64 t, %1; cvt.u32.u64 %0, t; }" : "=r"(a) : "l"(p));
    return a;
}
__device__ __forceinline__ void cpa16(u32 s, const void* g) {
    asm volatile("cp.async.cg.shared.global [%0], [%1], 16;" :: "r"(s), "l"(g));
}
__device__ __forceinline__ void ldsm4(u32& r0, u32& r1, u32& r2, u32& r3, u32 addr) {
    asm volatile("ldmatrix.sync.aligned.m8n8.x4.shared.b16 {%0,%1,%2,%3}, [%4];"
                 : "=r"(r0), "=r"(r1), "=r"(r2), "=r"(r3) : "r"(addr));
}

// ---------------- scratch (static device, no allocs) ----------------
__device__ float g_qk  [M1*512];
__device__ float g_v   [M1*Dm];
__device__ float g_tmp [M1*Dm];
__device__ float g_tgt [M1*Dm];
__device__ float g_tgt2[M1*Dm];
__device__ float g_value[(size_t)MV*Dm];
__device__ float g_off [M1*256];
__device__ float g_attw[M1*128];

#define AMAX ((size_t)MV*Dm)
__device__ __nv_bfloat16 g_ahi[AMAX];
__device__ __nv_bfloat16 g_alo[AMAX];
__device__ __nv_bfloat16 g_bhi[M1*DFF];
__device__ __nv_bfloat16 g_blo[M1*DFF];
#define WTOT 1015808
__device__ __nv_bfloat16 g_whi[WTOT];
__device__ __nv_bfloat16 g_wlo[WTOT];

#define WO_IN   0
#define WO_INV  131072
#define WO_OW   196608
#define WO_VW   262144
#define WO_OFF  327680
#define WO_AW   393216
#define WO_OP   425984
#define WO_L1   491520
#define WO_L2   753664

// ---------------- fp32 -> (bf16 hi, bf16 lo) split ----------------
__device__ __forceinline__ void split1(float x, __nv_bfloat16& h, __nv_bfloat16& l) {
    h = __float2bfloat16(x);
    l = __float2bfloat16(x - __bfloat162float(h));
}
__global__ void split_kernel(const float* __restrict__ x,
                             __nv_bfloat16* __restrict__ hi,
                             __nv_bfloat16* __restrict__ lo, int n4) {
    int i = blockIdx.x * blockDim.x + threadIdx.x;
    if (i < n4) {
        float4 v = ((const float4*)x)[i];
        __nv_bfloat16 h0,h1,h2,h3,l0,l1,l2,l3;
        split1(v.x,h0,l0); split1(v.y,h1,l1); split1(v.z,h2,l2); split1(v.w,h3,l3);
        ((__nv_bfloat162*)hi)[2*i]   = __nv_bfloat162(h0,h1);
        ((__nv_bfloat162*)hi)[2*i+1] = __nv_bfloat162(h2,h3);
        ((__nv_bfloat162*)lo)[2*i]   = __nv_bfloat162(l0,l1);
        ((__nv_bfloat162*)lo)[2*i+1] = __nv_bfloat162(l2,l3);
    }
}
__global__ void add_split_kernel(const float* __restrict__ a, const float* __restrict__ b,
                                 __nv_bfloat16* __restrict__ hi,
                                 __nv_bfloat16* __restrict__ lo, int n4) {
    int i = blockIdx.x * blockDim.x + threadIdx.x;
    if (i < n4) {
        float4 av = ((const float4*)a)[i];
        float4 bv = ((const float4*)b)[i];
        float4 v = make_float4(av.x+bv.x, av.y+bv.y, av.z+bv.z, av.w+bv.w);
        __nv_bfloat16 h0,h1,h2,h3,l0,l1,l2,l3;
        split1(v.x,h0,l0); split1(v.y,h1,l1); split1(v.z,h2,l2); split1(v.w,h3,l3);
        ((__nv_bfloat162*)hi)[2*i]   = __nv_bfloat162(h0,h1);
        ((__nv_bfloat162*)hi)[2*i+1] = __nv_bfloat162(h2,h3);
        ((__nv_bfloat162*)lo)[2*i]   = __nv_bfloat162(l0,l1);
        ((__nv_bfloat162*)lo)[2*i+1] = __nv_bfloat162(l2,l3);
    }
}

// ---------------- split-bf16 HMMA GEMM, cp.async + ldmatrix ----------------
// C = (Ahi+Alo)(MxK) @ (Whi+Wlo)(NxK)^T + bias; grid=(N/64, M/128), 256 thr.
#define SSTR 40
#define BUFB 30720
#define SMT  (2*BUFB)

__global__ __launch_bounds__(256) void mma_gemm(
    const __nv_bfloat16* __restrict__ Ahi, const __nv_bfloat16* __restrict__ Alo,
    const __nv_bfloat16* __restrict__ Whi, const __nv_bfloat16* __restrict__ Wlo,
    const float* __restrict__ bias, float* __restrict__ C,
    __nv_bfloat16* __restrict__ Chi, __nv_bfloat16* __restrict__ Clo,
    int K, int N, int relu, int splitout)
{
    extern __shared__ char smem[];
    const u32 sb = smem_u32(smem);

    const int tid  = threadIdx.x;
    const int lane = tid & 31, wid = tid >> 5;
    const int wm = wid >> 1, wn = wid & 1;
    const int m0 = blockIdx.y * 128, n0 = blockIdx.x * 64;
    const int r = lane >> 2, q = (lane & 3) * 2;
    // ldmatrix lane addressing
    const int g = lane >> 3, lr = lane & 7;
    const int rofs = lr + ((g & 1) << 3);
    const int cofs = (g >> 1) << 3;

    float acc[2][4][4];
    #pragma unroll
    for (int mi = 0; mi < 2; mi++)
        #pragma unroll
        for (int ni = 0; ni < 4; ni++)
            #pragma unroll
            for (int c = 0; c < 4; c++) acc[mi][ni][c] = 0.f;

    const int arow = tid >> 2;
    const int ac4  = tid & 3;

    const int nch = K >> 5;

    auto stage = [&](int buf, int kc) {
        u32 oah = sb + buf * BUFB;
        u32 oal = oah + 10240;
        u32 obh = oah + 20480;
        u32 obl = oah + 25600;
        #pragma unroll
        for (int it = 0; it < 2; it++) {
            int row = arow + it * 64;
            size_t gof = (size_t)(m0 + row) * K + kc + ac4 * 8;
            u32 so = (u32)(row * SSTR + ac4 * 8) * 2;
            cpa16(oah + so, Ahi + gof);
            cpa16(oal + so, Alo + gof);
        }
        {
            size_t gof = (size_t)(n0 + arow) * K + kc + ac4 * 8;
            u32 so = (u32)(arow * SSTR + ac4 * 8) * 2;
            cpa16(obh + so, Whi + gof);
            cpa16(obl + so, Wlo + gof);
        }
        asm volatile("cp.async.commit_group;" ::: "memory");
    };

    stage(0, 0);
    int buf = 0;
    for (int ck = 0; ck < nch; ck++) {
        const bool more = (ck + 1 < nch);
        if (more) stage(buf ^ 1, (ck + 1) << 5);
        if (more) asm volatile("cp.async.wait_group 1;" ::: "memory");
        else      asm volatile("cp.async.wait_group 0;" ::: "memory");
        __syncthreads();

        const u32 bb = sb + buf * BUFB;

        #pragma unroll
        for (int ks = 0; ks < 32; ks += 16) {
            u32 ah[2][4], al[2][4], bh[4][2], bl[4][2];
            #pragma unroll
            for (int mi = 0; mi < 2; mi++) {
                int row = wm*32 + mi*16 + rofs;
                u32 off = (u32)(row * SSTR + ks + cofs) * 2;
                ldsm4(ah[mi][0], ah[mi][1], ah[mi][2], ah[mi][3], bb + off);
                ldsm4(al[mi][0], al[mi][1], al[mi][2], al[mi][3], bb + 10240 + off);
            }
            #pragma unroll
            for (int nip = 0; nip < 2; nip++) {
                int row = wn*32 + nip*16 + rofs;
                u32 off = (u32)(row * SSTR + ks + cofs) * 2;
                // ldmatrix x4 order: r0 = n0-7/k0-7 (b0 tile0), r1 = n8-15/k0-7 (b0 tile1),
                //                    r2 = n0-7/k8-15 (b1 tile0), r3 = n8-15/k8-15 (b1 tile1)
                ldsm4(bh[2*nip][0], bh[2*nip+1][0], bh[2*nip][1], bh[2*nip+1][1], bb + 20480 + off);
                ldsm4(bl[2*nip][0], bl[2*nip+1][0], bl[2*nip][1], bl[2*nip+1][1], bb + 25600 + off);
            }
            #pragma unroll
            for (int mi = 0; mi < 2; mi++)
                #pragma unroll
                for (int ni = 0; ni < 4; ni++) {
                    mma16816(acc[mi][ni], ah[mi], bh[ni]);
                    mma16816(acc[mi][ni], ah[mi], bl[ni]);
                    mma16816(acc[mi][ni], al[mi], bh[ni]);
                }
        }
        __syncthreads();
        buf ^= 1;
    }

    // ---- epilogue ----
    #pragma unroll
    for (int mi = 0; mi < 2; mi++) {
        int row0 = m0 + wm*32 + mi*16 + r;
        #pragma unroll
        for (int ni = 0; ni < 4; ni++) {
            int col = n0 + wn*32 + ni*8 + q;
            float2 bv = *(const float2*)(bias + col);
            float2 v0 = make_float2(acc[mi][ni][0] + bv.x, acc[mi][ni][1] + bv.y);
            float2 v1 = make_float2(acc[mi][ni][2] + bv.x, acc[mi][ni][3] + bv.y);
            if (relu) {
                v0.x = fmaxf(v0.x, 0.f); v0.y = fmaxf(v0.y, 0.f);
                v1.x = fmaxf(v1.x, 0.f); v1.y = fmaxf(v1.y, 0.f);
            }
            if (splitout) {
                __nv_bfloat16 h0,l0,h1,l1,h2,l2,h3,l3;
                split1(v0.x,h0,l0); split1(v0.y,h1,l1);
                split1(v1.x,h2,l2); split1(v1.y,h3,l3);
                *(__nv_bfloat162*)&Chi[(size_t)row0     * N + col] = __nv_bfloat162(h0,h1);
                *(__nv_bfloat162*)&Clo[(size_t)row0     * N + col] = __nv_bfloat162(l0,l1);
                *(__nv_bfloat162*)&Chi[(size_t)(row0+8) * N + col] = __nv_bfloat162(h2,h3);
                *(__nv_bfloat162*)&Clo[(size_t)(row0+8) * N + col] = __nv_bfloat162(l2,l3);
            } else {
                *(float2*)(C + (size_t)row0     * N + col) = v0;
                *(float2*)(C + (size_t)(row0+8) * N + col) = v1;
            }
        }
    }
}

// ---------------- flash attention (f32x2 core, split-bf16 output) ----------------
#define ATQ 128
#define KC  32
__global__ __launch_bounds__(ATQ) void attn_kernel(
    const float* __restrict__ QK, const float* __restrict__ V,
    __nv_bfloat16* __restrict__ Ohi, __nv_bfloat16* __restrict__ Olo)
{
    __shared__ float Ks[KC][32];
    __shared__ float Vs[KC][32];
    __shared__ float Ss[ATQ][KC + 1];
    const int t = threadIdx.x;
    const int bh = blockIdx.y, b = bh >> 3, h = bh & 7;
    const int q = blockIdx.x * ATQ + t;

    const float4* qp = (const float4*)(QK + ((size_t)(b*LQ + q))*512 + h*DH);
    float4 qv[8];
    #pragma unroll
    for (int i = 0; i < 8; i++) qv[i] = qp[i];
    const u64* q2 = (const u64*)qv;

    u64 o2[16];
    #pragma unroll
    for (int i = 0; i < 16; i++) o2[i] = 0ull;
    float m = -1e30f, l = 0.f;
    const float scale = 0.17677669529663687f;

    const int sr0 = t >> 3;
    const int sc  = t & 7;

    for (int kc = 0; kc < LQ; kc += KC) {
        #pragma unroll
        for (int ph = 0; ph < 2; ph++) {
            int row = sr0 + ph*16;
            const float4* kp = (const float4*)(QK + ((size_t)(b*LQ + kc + row))*512 + 256 + h*DH);
            const float4* vp = (const float4*)(V  + ((size_t)(b*LQ + kc + row))*Dm  + h*DH);
            *((float4*)Ks[row] + sc) = kp[sc];
            *((float4*)Vs[row] + sc) = vp[sc];
        }
        __syncthreads();

        float cmax = -1e30f;
        #pragma unroll 8
        for (int j = 0; j < KC; j++) {
            const u64* kk = (const u64*)Ks[j];
            u64 d2 = 0ull;
            #pragma unroll
            for (int i = 0; i < 16; i++) ffma2(d2, q2[i], kk[i]);
            float2 dd = unpack2(d2);
            float d = (dd.x + dd.y) * scale;
            Ss[t][j] = d;
            cmax = fmaxf(cmax, d);
        }
        float mnew = fmaxf(m, cmax);
        float corr = __expf(m - mnew);
        l *= corr;
        u64 cc = pack2(corr, corr);
        #pragma unroll
        for (int i = 0; i < 16; i++) fmul2(o2[i], cc);

        #pragma unroll 4
        for (int j = 0; j < KC; j++) {
            float p = __expf(Ss[t][j] - mnew);
            l += p;
            u64 pp = pack2(p, p);
            const u64* vv = (const u64*)Vs[j];
            #pragma unroll
            for (int i = 0; i < 16; i++) ffma2(o2[i], pp, vv[i]);
        }
        m = mnew;
        __syncthreads();
    }

    float inv = 1.f / l;
    u64 iv = pack2(inv, inv);
    size_t base = ((size_t)(b*LQ + q))*Dm + h*DH;
    #pragma unroll
    for (int i = 0; i < 16; i++) {
        fmul2(o2[i], iv);
        float2 f = unpack2(o2[i]);
        __nv_bfloat16 h0,l0,h1,l1;
        split1(f.x,h0,l0); split1(f.y,h1,l1);
        *(__nv_bfloat162*)&Ohi[base + 2*i] = __nv_bfloat162(h0,h1);
        *(__nv_bfloat162*)&Olo[base + 2*i] = __nv_bfloat162(l0,l1);
    }
}

// ---------------- layernorm(a + b) * g + beta (optional split out) ----------------
template<int SPLIT>
__global__ __launch_bounds__(256) void ln_kernel_t(
    const float* __restrict__ a, const float* __restrict__ b,
    const float* __restrict__ g, const float* __restrict__ be,
    float* __restrict__ out,
    __nv_bfloat16* __restrict__ ohi, __nv_bfloat16* __restrict__ olo)
{
    __shared__ float red[8];
    int row = blockIdx.x, t = threadIdx.x;
    float x = a[(size_t)row*Dm + t] + b[(size_t)row*Dm + t];

    float s = x;
    #pragma unroll
    for (int o = 16; o; o >>= 1) s += __shfl_xor_sync(0xffffffffu, s, o);
    if ((t & 31) == 0) red[t >> 5] = s;
    __syncthreads();
    float tot = 0.f;
    #pragma unroll
    for (int i = 0; i < 8; i++) tot += red[i];
    float mean = tot * (1.f / Dm);
    float d0 = x - mean;
    __syncthreads();

    float sq = d0 * d0;
    #pragma unroll
    for (int o = 16; o; o >>= 1) sq += __shfl_xor_sync(0xffffffffu, sq, o);
    if ((t & 31) == 0) red[t >> 5] = sq;
    __syncthreads();
    float tot2 = 0.f;
    #pragma unroll
    for (int i = 0; i < 8; i++) tot2 += red[i];
    float var = tot2 * (1.f / Dm);

    float y = d0 * rsqrtf(var + EPSV) * g[t] + be[t];
    out[(size_t)row*Dm + t] = y;
    if (SPLIT) {
        __nv_bfloat16 h, lo_;
        split1(y, h, lo_);
        ohi[(size_t)row*Dm + t] = h;
        olo[(size_t)row*Dm + t] = lo_;
    }
}

// ---------------- deformable sampler (attw softmax fused, split out) ----------------
__global__ __launch_bounds__(256) void sampler_kernel(
    const float* __restrict__ refp,
    const float* __restrict__ off,
    const float* __restrict__ attw,
    const float* __restrict__ value,
    __nv_bfloat16* __restrict__ shi, __nv_bfloat16* __restrict__ slo)
{
    int bq = blockIdx.x;
    int b = bq >> 10;
    int t = threadIdx.x;
    int h = t >> 5, lane = t & 31;

    float logit = (lane < 16) ? attw[(size_t)bq*128 + h*16 + lane] : -1e30f;
    float mx = logit;
    #pragma unroll
    for (int o = 16; o; o >>= 1) mx = fmaxf(mx, __shfl_xor_sync(0xffffffffu, mx, o));
    float e = (lane < 16) ? __expf(logit - mx) : 0.f;
    float sum = e;
    #pragma unroll
    for (int o = 16; o; o >>= 1) sum += __shfl_xor_sync(0xffffffffu, sum, o);
    float aw_lane = e / sum;

    const int wls[4]    = {64, 32, 16, 8};
    const int hls[4]    = {64, 32, 16, 8};
    const int starts[4] = {0, 4096, 5120, 5376};

    const float* rp = refp + ((size_t)bq * Ll) * 2;
    float acc = 0.f;

    #pragma unroll
    for (int l = 0; l < Ll; l++) {
        int wl = wls[l], hl = hls[l], st = starts[l];
        float rx = rp[l*2 + 0];
        float ry = rp[l*2 + 1];
        #pragma unroll
        for (int p = 0; p < Pp; p++) {
            int n = (h*Ll + l)*Pp + p;
            float ox = off[(size_t)bq*256 + n*2 + 0];
            float oy = off[(size_t)bq*256 + n*2 + 1];
            float x = (rx + ox / (float)wl) * (float)wl - 0.5f;
            float y = (ry + oy / (float)hl) * (float)hl - 0.5f;
            float x0f = floorf(x), y0f = floorf(y);
            float lx = x - x0f, ly = y - y0f;
            int x0 = (int)x0f, y0 = (int)y0f;
            float aw = __shfl_sync(0xffffffffu, aw_lane, l*Pp + p);

            float g00 = 0.f, g01 = 0.f, g10 = 0.f, g11 = 0.f;
            if (x0   >= 0 && x0   < wl && y0   >= 0 && y0   < hl)
                g00 = value[((size_t)(b*LV + st + y0*wl + x0))*Dm + h*DH + lane];
            if (x0+1 >= 0 && x0+1 < wl && y0   >= 0 && y0   < hl)
                g01 = value[((size_t)(b*LV + st + y0*wl + x0+1))*Dm + h*DH + lane];
            if (x0   >= 0 && x0   < wl && y0+1 >= 0 && y0+1 < hl)
                g10 = value[((size_t)(b*LV + st + (y0+1)*wl + x0))*Dm + h*DH + lane];
            if (x0+1 >= 0 && x0+1 < wl && y0+1 >= 0 && y0+1 < hl)
                g11 = value[((size_t)(b*LV + st + (y0+1)*wl + x0+1))*Dm + h*DH + lane];

            float sv = g00*(1.f-lx)*(1.f-ly) + g01*lx*(1.f-ly)
                     + g10*(1.f-lx)*ly       + g11*lx*ly;
            acc += aw * sv;
        }
    }
    __nv_bfloat16 hh, ll;
    split1(acc, hh, ll);
    shi[(size_t)bq*Dm + h*DH + lane] = hh;
    slo[(size_t)bq*Dm + h*DH + lane] = ll;
}

// ---------------- launch ----------------
extern "C" void kernel_launch(void* const* d_in, const int* in_sizes, int n_in,
                              void* d_out, int out_size) {
    const float* tgt  = (const float*)d_in[0];
    const float* qpos = (const float*)d_in[1];
    const float* refp = (const float*)d_in[2];
    const float* src  = (const float*)d_in[3];
    const float* in_w = (const float*)d_in[4];
    const float* in_b = (const float*)d_in[5];
    const float* ow   = (const float*)d_in[6];
    const float* ob   = (const float*)d_in[7];
    const float* n2g  = (const float*)d_in[8];
    const float* n2b  = (const float*)d_in[9];
    const float* vw   = (const float*)d_in[10];
    const float* vb   = (const float*)d_in[11];
    const float* offw = (const float*)d_in[12];
    const float* offb = (const float*)d_in[13];
    const float* aww  = (const float*)d_in[14];
    const float* awb  = (const float*)d_in[15];
    const float* opw  = (const float*)d_in[16];
    const float* opb  = (const float*)d_in[17];
    const float* n1g  = (const float*)d_in[18];
    const float* n1b  = (const float*)d_in[19];
    const float* l1w  = (const float*)d_in[20];
    const float* l1b  = (const float*)d_in[21];
    const float* l2w  = (const float*)d_in[22];
    const float* l2b  = (const float*)d_in[23];
    const float* n3g  = (const float*)d_in[24];
    const float* n3b  = (const float*)d_in[25];
    float* out = (float*)d_out;

    float *p_qk, *p_v, *p_tmp, *p_tgt, *p_tgt2, *p_value, *p_off, *p_attw;
    __nv_bfloat16 *p_ahi, *p_alo, *p_bhi, *p_blo, *p_whi, *p_wlo;
    cudaGetSymbolAddress((void**)&p_qk,   g_qk);
    cudaGetSymbolAddress((void**)&p_v,    g_v);
    cudaGetSymbolAddress((void**)&p_tmp,  g_tmp);
    cudaGetSymbolAddress((void**)&p_tgt,  g_tgt);
    cudaGetSymbolAddress((void**)&p_tgt2, g_tgt2);
    cudaGetSymbolAddress((void**)&p_value,g_value);
    cudaGetSymbolAddress((void**)&p_off,  g_off);
    cudaGetSymbolAddress((void**)&p_attw, g_attw);
    cudaGetSymbolAddress((void**)&p_ahi,  g_ahi);
    cudaGetSymbolAddress((void**)&p_alo,  g_alo);
    cudaGetSymbolAddress((void**)&p_bhi,  g_bhi);
    cudaGetSymbolAddress((void**)&p_blo,  g_blo);
    cudaGetSymbolAddress((void**)&p_whi,  g_whi);
    cudaGetSymbolAddress((void**)&p_wlo,  g_wlo);

    cudaFuncSetAttribute(mma_gemm, cudaFuncAttributeMaxDynamicSharedMemorySize, SMT);

    const int n4 = M1 * Dm / 4;

    // ---- weight splits ----
    #define SPL(src_, off_, n_) split_kernel<<<((n_)/4 + 255)/256, 256>>>(src_, p_whi + (off_), p_wlo + (off_), (n_)/4)
    SPL(in_w, WO_IN,  768*256);
    SPL(ow,   WO_OW,  65536);
    SPL(vw,   WO_VW,  65536);
    SPL(offw, WO_OFF, 65536);
    SPL(aww,  WO_AW,  32768);
    SPL(opw,  WO_OP,  65536);
    SPL(l1w,  WO_L1,  262144);
    SPL(l2w,  WO_L2,  262144);
    #undef SPL

    // 1. q = tgt + qpos -> bf16 split
    add_split_kernel<<<(n4 + 255)/256, 256>>>(tgt, qpos, p_ahi, p_alo, n4);
    // 2. [Q|K] = q @ in_w[0:512].T + b
    mma_gemm<<<dim3(8, M1/128), 256, SMT>>>(p_ahi, p_alo, p_whi + WO_IN, p_wlo + WO_IN, in_b, p_qk, 0, 0, 256, 512, 0, 0);
    // 3. V = tgt @ in_w[512:768].T + b
    split_kernel<<<(n4 + 255)/256, 256>>>(tgt, p_ahi, p_alo, n4);
    mma_gemm<<<dim3(4, M1/128), 256, SMT>>>(p_ahi, p_alo, p_whi + WO_INV, p_wlo + WO_INV, in_b + 512, p_v, 0, 0, 256, 256, 0, 0);
    // 4. attention (writes split att directly)
    attn_kernel<<<dim3(LQ/ATQ, Bq*Hh), ATQ>>>(p_qk, p_v, p_ahi, p_alo);
    // 5. out_proj
    mma_gemm<<<dim3(4, M1/128), 256, SMT>>>(p_ahi, p_alo, p_whi + WO_OW, p_wlo + WO_OW, ob, p_tmp, 0, 0, 256, 256, 0, 0);
    // 6. tgt = LN(tgt + tgt2, norm2)
    ln_kernel_t<0><<<M1, 256>>>(tgt, p_tmp, n2g, n2b, p_tgt, 0, 0);
    // 7. q2 = tgt + qpos -> off + attw projections
    add_split_kernel<<<(n4 + 255)/256, 256>>>(p_tgt, qpos, p_ahi, p_alo, n4);
    mma_gemm<<<dim3(4, M1/128), 256, SMT>>>(p_ahi, p_alo, p_whi + WO_OFF, p_wlo + WO_OFF, offb, p_off, 0, 0, 256, 256, 0, 0);
    mma_gemm<<<dim3(2, M1/128), 256, SMT>>>(p_ahi, p_alo, p_whi + WO_AW, p_wlo + WO_AW, awb, p_attw, 0, 0, 256, 128, 0, 0);
    // 8. value = src @ value_w.T + b
    split_kernel<<<((int)(MV*(size_t)Dm/4) + 255)/256, 256>>>(src, p_ahi, p_alo, (int)(MV*(size_t)Dm/4));
    mma_gemm<<<dim3(4, MV/128), 256, SMT>>>(p_ahi, p_alo, p_whi + WO_VW, p_wlo + WO_VW, vb, p_value, 0, 0, 256, 256, 0, 0);
    // 9. sampler (writes split samp directly)
    sampler_kernel<<<M1, 256>>>(refp, p_off, p_attw, p_value, p_ahi, p_alo);
    // 10. outp proj
    mma_gemm<<<dim3(4, M1/128), 256, SMT>>>(p_ahi, p_alo, p_whi + WO_OP, p_wlo + WO_OP, opb, p_tmp, 0, 0, 256, 256, 0, 0);
    // 11. tgt2 = LN(tgt + t, norm1) -> fp32 + split
    ln_kernel_t<1><<<M1, 256>>>(p_tgt, p_tmp, n1g, n1b, p_tgt2, p_ahi, p_alo);
    // 12. ffn mid = relu(tgt2 @ l1w.T + b) -> split output
    mma_gemm<<<dim3(16, M1/128), 256, SMT>>>(p_ahi, p_alo, p_whi + WO_L1, p_wlo + WO_L1, l1b, 0, p_bhi, p_blo, 256, 1024, 1, 1);
    // 13. ffn out
    mma_gemm<<<dim3(4, M1/128), 256, SMT>>>(p_bhi, p_blo, p_whi + WO_L2, p_wlo + WO_L2, l2b, p_tmp, 0, 0, 1024, 256, 0, 0);
    // 14. out = LN(tgt2 + t2, norm3)
    ln_kernel_t<0><<<M1, 256>>>(p_tgt2, p_tmp, n3g, n3b, out, 0, 0);
}

// round 17
// speedup vs baseline: 1.3474x; 1.3474x over previous
#include <cuda_runtime.h>
#include <cuda_bf16.h>
#include <math.h>
#include <stdint.h>

// ---------------- problem constants ----------------
#define Bq   16
#define LQ   1024
#define Dm   256
#define Hh   8
#define Ll   4
#define Pp   4
#define DFF  1024
#define DH   32
#define LV   5440
#define M1   (Bq*LQ)       // 16384
#define MV   (Bq*LV)       // 87040
#define EPSV 1e-5f

typedef unsigned long long u64;
typedef uint32_t u32;

// ---------------- HMMA + cp.async + ldmatrix helpers ----------------
__device__ __forceinline__ void mma16816(float* c, const u32* a, const u32* b) {
    asm volatile(
        "mma.sync.aligned.m16n8k16.row.col.f32.bf16.bf16.f32 "
        "{%0,%1,%2,%3}, {%4,%5,%6,%7}, {%8,%9}, {%0,%1,%2,%3};"
        : "+f"(c[0]), "+f"(c[1]), "+f"(c[2]), "+f"(c[3])
        : "r"(a[0]), "r"(a[1]), "r"(a[2]), "r"(a[3]), "r"(b[0]), "r"(b[1]));
}
__device__ __forceinline__ u32 smem_u32(const void* p) {
    u32 a;
    asm("{ .reg .u64 t; cvta.to.shared.u64 t, %1; cvt.u32.u64 %0, t; }" : "=r"(a) : "l"(p));
    return a;
}
__device__ __forceinline__ void cpa16(u32 s, const void* g) {
    asm volatile("cp.async.cg.shared.global [%0], [%1], 16;" :: "r"(s), "l"(g));
}
__device__ __forceinline__ void ldsm4(u32& r0, u32& r1, u32& r2, u32& r3, u32 addr) {
    asm volatile("ldmatrix.sync.aligned.m8n8.x4.shared.b16 {%0,%1,%2,%3}, [%4];"
                 : "=r"(r0), "=r"(r1), "=r"(r2), "=r"(r3) : "r"(addr));
}
__device__ __forceinline__ void ldsm4t(u32& r0, u32& r1, u32& r2, u32& r3, u32 addr) {
    asm volatile("ldmatrix.sync.aligned.m8n8.x4.trans.shared.b16 {%0,%1,%2,%3}, [%4];"
                 : "=r"(r0), "=r"(r1), "=r"(r2), "=r"(r3) : "r"(addr));
}

// ---------------- scratch (static device, no allocs) ----------------
__device__ float g_tmp [M1*Dm];
__device__ float g_tgt [M1*Dm];
__device__ float g_tgt2[M1*Dm];
__device__ float g_value[(size_t)MV*Dm];
__device__ float g_off [M1*256];
__device__ float g_attw[M1*128];

#define AMAX ((size_t)MV*Dm)
__device__ __nv_bfloat16 g_ahi[AMAX];
__device__ __nv_bfloat16 g_alo[AMAX];
__device__ __nv_bfloat16 g_bhi[M1*DFF];   // also Q|K hi (M1 x 512)
__device__ __nv_bfloat16 g_blo[M1*DFF];   // also Q|K lo
__device__ __nv_bfloat16 g_vhi[M1*Dm];
__device__ __nv_bfloat16 g_vlo[M1*Dm];
#define WTOT 1015808
__device__ __nv_bfloat16 g_whi[WTOT];
__device__ __nv_bfloat16 g_wlo[WTOT];

#define WO_IN   0
#define WO_INV  131072
#define WO_OW   196608
#define WO_VW   262144
#define WO_OFF  327680
#define WO_AW   393216
#define WO_OP   425984
#define WO_L1   491520
#define WO_L2   753664

// ---------------- fp32 -> (bf16 hi, bf16 lo) split ----------------
__device__ __forceinline__ void split1(float x, __nv_bfloat16& h, __nv_bfloat16& l) {
    h = __float2bfloat16(x);
    l = __float2bfloat16(x - __bfloat162float(h));
}
__device__ __forceinline__ u32 pack_bf2(float a, float b) {
    __nv_bfloat162 v(__float2bfloat16(a), __float2bfloat16(b));
    return *(u32*)&v;
}
__global__ void split_kernel(const float* __restrict__ x,
                             __nv_bfloat16* __restrict__ hi,
                             __nv_bfloat16* __restrict__ lo, int n4) {
    int i = blockIdx.x * blockDim.x + threadIdx.x;
    if (i < n4) {
        float4 v = ((const float4*)x)[i];
        __nv_bfloat16 h0,h1,h2,h3,l0,l1,l2,l3;
        split1(v.x,h0,l0); split1(v.y,h1,l1); split1(v.z,h2,l2); split1(v.w,h3,l3);
        ((__nv_bfloat162*)hi)[2*i]   = __nv_bfloat162(h0,h1);
        ((__nv_bfloat162*)hi)[2*i+1] = __nv_bfloat162(h2,h3);
        ((__nv_bfloat162*)lo)[2*i]   = __nv_bfloat162(l0,l1);
        ((__nv_bfloat162*)lo)[2*i+1] = __nv_bfloat162(l2,l3);
    }
}
__global__ void add_split_kernel(const float* __restrict__ a, const float* __restrict__ b,
                                 __nv_bfloat16* __restrict__ hi,
                                 __nv_bfloat16* __restrict__ lo, int n4) {
    int i = blockIdx.x * blockDim.x + threadIdx.x;
    if (i < n4) {
        float4 av = ((const float4*)a)[i];
        float4 bv = ((const float4*)b)[i];
        float4 v = make_float4(av.x+bv.x, av.y+bv.y, av.z+bv.z, av.w+bv.w);
        __nv_bfloat16 h0,h1,h2,h3,l0,l1,l2,l3;
        split1(v.x,h0,l0); split1(v.y,h1,l1); split1(v.z,h2,l2); split1(v.w,h3,l3);
        ((__nv_bfloat162*)hi)[2*i]   = __nv_bfloat162(h0,h1);
        ((__nv_bfloat162*)hi)[2*i+1] = __nv_bfloat162(h2,h3);
        ((__nv_bfloat162*)lo)[2*i]   = __nv_bfloat162(l0,l1);
        ((__nv_bfloat162*)lo)[2*i+1] = __nv_bfloat162(l2,l3);
    }
}

// ---------------- split-bf16 HMMA GEMM, cp.async + ldmatrix ----------------
#define SSTR 40
#define BUFB 30720
#define SMT  (2*BUFB)

__global__ __launch_bounds__(256) void mma_gemm(
    const __nv_bfloat16* __restrict__ Ahi, const __nv_bfloat16* __restrict__ Alo,
    const __nv_bfloat16* __restrict__ Whi, const __nv_bfloat16* __restrict__ Wlo,
    const float* __restrict__ bias, float* __restrict__ C,
    __nv_bfloat16* __restrict__ Chi, __nv_bfloat16* __restrict__ Clo,
    int K, int N, int relu, int splitout)
{
    extern __shared__ char smem[];
    const u32 sb = smem_u32(smem);

    const int tid  = threadIdx.x;
    const int lane = tid & 31, wid = tid >> 5;
    const int wm = wid >> 1, wn = wid & 1;
    const int m0 = blockIdx.y * 128, n0 = blockIdx.x * 64;
    const int r = lane >> 2, q = (lane & 3) * 2;
    const int g = lane >> 3, lr = lane & 7;
    const int rofs = lr + ((g & 1) << 3);
    const int cofs = (g >> 1) << 3;

    float acc[2][4][4];
    #pragma unroll
    for (int mi = 0; mi < 2; mi++)
        #pragma unroll
        for (int ni = 0; ni < 4; ni++)
            #pragma unroll
            for (int c = 0; c < 4; c++) acc[mi][ni][c] = 0.f;

    const int arow = tid >> 2;
    const int ac4  = tid & 3;
    const int nch = K >> 5;

    auto stage = [&](int buf, int kc) {
        u32 oah = sb + buf * BUFB;
        u32 oal = oah + 10240;
        u32 obh = oah + 20480;
        u32 obl = oah + 25600;
        #pragma unroll
        for (int it = 0; it < 2; it++) {
            int row = arow + it * 64;
            size_t gof = (size_t)(m0 + row) * K + kc + ac4 * 8;
            u32 so = (u32)(row * SSTR + ac4 * 8) * 2;
            cpa16(oah + so, Ahi + gof);
            cpa16(oal + so, Alo + gof);
        }
        {
            size_t gof = (size_t)(n0 + arow) * K + kc + ac4 * 8;
            u32 so = (u32)(arow * SSTR + ac4 * 8) * 2;
            cpa16(obh + so, Whi + gof);
            cpa16(obl + so, Wlo + gof);
        }
        asm volatile("cp.async.commit_group;" ::: "memory");
    };

    stage(0, 0);
    int buf = 0;
    for (int ck = 0; ck < nch; ck++) {
        const bool more = (ck + 1 < nch);
        if (more) stage(buf ^ 1, (ck + 1) << 5);
        if (more) asm volatile("cp.async.wait_group 1;" ::: "memory");
        else      asm volatile("cp.async.wait_group 0;" ::: "memory");
        __syncthreads();

        const u32 bb = sb + buf * BUFB;

        #pragma unroll
        for (int ks = 0; ks < 32; ks += 16) {
            u32 ah[2][4], al[2][4], bh[4][2], bl[4][2];
            #pragma unroll
            for (int mi = 0; mi < 2; mi++) {
                int row = wm*32 + mi*16 + rofs;
                u32 off = (u32)(row * SSTR + ks + cofs) * 2;
                ldsm4(ah[mi][0], ah[mi][1], ah[mi][2], ah[mi][3], bb + off);
                ldsm4(al[mi][0], al[mi][1], al[mi][2], al[mi][3], bb + 10240 + off);
            }
            #pragma unroll
            for (int nip = 0; nip < 2; nip++) {
                int row = wn*32 + nip*16 + rofs;
                u32 off = (u32)(row * SSTR + ks + cofs) * 2;
                ldsm4(bh[2*nip][0], bh[2*nip+1][0], bh[2*nip][1], bh[2*nip+1][1], bb + 20480 + off);
                ldsm4(bl[2*nip][0], bl[2*nip+1][0], bl[2*nip][1], bl[2*nip+1][1], bb + 25600 + off);
            }
            #pragma unroll
            for (int mi = 0; mi < 2; mi++)
                #pragma unroll
                for (int ni = 0; ni < 4; ni++) {
                    mma16816(acc[mi][ni], ah[mi], bh[ni]);
                    mma16816(acc[mi][ni], ah[mi], bl[ni]);
                    mma16816(acc[mi][ni], al[mi], bh[ni]);
                }
        }
        __syncthreads();
        buf ^= 1;
    }

    #pragma unroll
    for (int mi = 0; mi < 2; mi++) {
        int row0 = m0 + wm*32 + mi*16 + r;
        #pragma unroll
        for (int ni = 0; ni < 4; ni++) {
            int col = n0 + wn*32 + ni*8 + q;
            float2 bv = *(const float2*)(bias + col);
            float2 v0 = make_float2(acc[mi][ni][0] + bv.x, acc[mi][ni][1] + bv.y);
            float2 v1 = make_float2(acc[mi][ni][2] + bv.x, acc[mi][ni][3] + bv.y);
            if (relu) {
                v0.x = fmaxf(v0.x, 0.f); v0.y = fmaxf(v0.y, 0.f);
                v1.x = fmaxf(v1.x, 0.f); v1.y = fmaxf(v1.y, 0.f);
            }
            if (splitout) {
                __nv_bfloat16 h0,l0,h1,l1,h2,l2,h3,l3;
                split1(v0.x,h0,l0); split1(v0.y,h1,l1);
                split1(v1.x,h2,l2); split1(v1.y,h3,l3);
                *(__nv_bfloat162*)&Chi[(size_t)row0     * N + col] = __nv_bfloat162(h0,h1);
                *(__nv_bfloat162*)&Clo[(size_t)row0     * N + col] = __nv_bfloat162(l0,l1);
                *(__nv_bfloat162*)&Chi[(size_t)(row0+8) * N + col] = __nv_bfloat162(h2,h3);
                *(__nv_bfloat162*)&Clo[(size_t)(row0+8) * N + col] = __nv_bfloat162(l2,l3);
            } else {
                *(float2*)(C + (size_t)row0     * N + col) = v0;
                *(float2*)(C + (size_t)(row0+8) * N + col) = v1;
            }
        }
    }
}

// ---------------- HMMA flash attention ----------------
// Block: 64 queries for one (b,h); 4 warps (16 q-rows each); key chunks of 64.
// QK buffer layout: row = b*LQ+token, 512 cols (Q: h*32.., K: 256+h*32..)
// smem per buffer: Khi[64][40] | Klo | Vhi | Vlo  (5120 B each) = 20480; x2 buffers.
#define ATSTR 40
#define ATBUF 20480
__global__ __launch_bounds__(128) void attn_mma(
    const __nv_bfloat16* __restrict__ QKhi, const __nv_bfloat16* __restrict__ QKlo,
    const __nv_bfloat16* __restrict__ Vhi,  const __nv_bfloat16* __restrict__ Vlo,
    __nv_bfloat16* __restrict__ Ohi, __nv_bfloat16* __restrict__ Olo)
{
    __shared__ char smem[2*ATBUF];
    const u32 sb = smem_u32(smem);
    const int tid = threadIdx.x;
    const int lane = tid & 31, wm = tid >> 5;
    const int b = blockIdx.y >> 3, h = blockIdx.y & 7;
    const int q0 = blockIdx.x * 64 + wm * 16;         // warp's first query row
    const int r = lane >> 2, q2 = (lane & 3) * 2;
    const int g = lane >> 3, lr = lane & 7;
    const int rofs = lr + ((g & 1) << 3);
    const int cofs = (g >> 1) << 3;
    const float scale = 0.17677669529663687f;          // 1/sqrt(32)

    // ---- Q fragments (persistent): qh/ql[kstep][4] ----
    u32 qh[2][4], ql[2][4];
    {
        size_t r0 = (size_t)(b*LQ + q0 + r    ) * 512 + h*32;
        size_t r8 = (size_t)(b*LQ + q0 + r + 8) * 512 + h*32;
        #pragma unroll
        for (int ks = 0; ks < 2; ks++) {
            qh[ks][0] = *(const u32*)&QKhi[r0 + ks*16 + q2];
            qh[ks][1] = *(const u32*)&QKhi[r8 + ks*16 + q2];
            qh[ks][2] = *(const u32*)&QKhi[r0 + ks*16 + q2 + 8];
            qh[ks][3] = *(const u32*)&QKhi[r8 + ks*16 + q2 + 8];
            ql[ks][0] = *(const u32*)&QKlo[r0 + ks*16 + q2];
            ql[ks][1] = *(const u32*)&QKlo[r8 + ks*16 + q2];
            ql[ks][2] = *(const u32*)&QKlo[r0 + ks*16 + q2 + 8];
            ql[ks][3] = *(const u32*)&QKlo[r8 + ks*16 + q2 + 8];
        }
    }

    float oacc[4][4];
    #pragma unroll
    for (int n = 0; n < 4; n++)
        #pragma unroll
        for (int c = 0; c < 4; c++) oacc[n][c] = 0.f;
    float m0 = -1e30f, m1 = -1e30f, l0 = 0.f, l1 = 0.f;

    // staging: 1024 cpa16 per chunk, 8 per thread.  arr: 0=Khi 1=Klo 2=Vhi 3=Vlo
    auto stage = [&](int buf, int kc) {
        u32 base = sb + buf * ATBUF;
        #pragma unroll
        for (int i = 0; i < 8; i++) {
            int gi  = i * 128 + tid;
            int arr = gi >> 8, rem = gi & 255;
            int row = rem >> 2, seg = rem & 3;
            u32 dst = base + arr * 5120 + (u32)(row * ATSTR + seg * 8) * 2;
            size_t tok = (size_t)(b*LQ + kc + row);
            const __nv_bfloat16* src;
            if (arr == 0)      src = QKhi + tok*512 + 256 + h*32 + seg*8;
            else if (arr == 1) src = QKlo + tok*512 + 256 + h*32 + seg*8;
            else if (arr == 2) src = Vhi  + tok*256 + h*32 + seg*8;
            else               src = Vlo  + tok*256 + h*32 + seg*8;
            cpa16(dst, src);
        }
        asm volatile("cp.async.commit_group;" ::: "memory");
    };

    stage(0, 0);
    int buf = 0;
    for (int kc = 0; kc < LQ; kc += 64) {
        const bool more = (kc + 64 < LQ);
        if (more) stage(buf ^ 1, kc + 64);
        if (more) asm volatile("cp.async.wait_group 1;" ::: "memory");
        else      asm volatile("cp.async.wait_group 0;" ::: "memory");
        __syncthreads();

        const u32 bb = sb + buf * ATBUF;

        // ---- S = Q @ K^T (3-term), 8 n-tiles of 8 keys ----
        float sacc[8][4];
        #pragma unroll
        for (int t = 0; t < 8; t++)
            #pragma unroll
            for (int c = 0; c < 4; c++) sacc[t][c] = 0.f;

        #pragma unroll
        for (int ks = 0; ks < 2; ks++) {
            u32 kh[8][2], kl[8][2];
            #pragma unroll
            for (int nip = 0; nip < 4; nip++) {
                u32 off = (u32)((nip*16 + rofs) * ATSTR + ks*16 + cofs) * 2;
                ldsm4(kh[2*nip][0], kh[2*nip+1][0], kh[2*nip][1], kh[2*nip+1][1], bb + off);
                ldsm4(kl[2*nip][0], kl[2*nip+1][0], kl[2*nip][1], kl[2*nip+1][1], bb + 5120 + off);
            }
            #pragma unroll
            for (int t = 0; t < 8; t++) {
                mma16816(sacc[t], qh[ks], kh[t]);
                mma16816(sacc[t], qh[ks], kl[t]);
                mma16816(sacc[t], ql[ks], kh[t]);
            }
        }

        // ---- online softmax (rows r and r+8) ----
        float mx0 = -1e30f, mx1 = -1e30f;
        #pragma unroll
        for (int t = 0; t < 8; t++) {
            mx0 = fmaxf(mx0, fmaxf(sacc[t][0], sacc[t][1]));
            mx1 = fmaxf(mx1, fmaxf(sacc[t][2], sacc[t][3]));
        }
        mx0 = fmaxf(mx0, __shfl_xor_sync(0xffffffffu, mx0, 1));
        mx0 = fmaxf(mx0, __shfl_xor_sync(0xffffffffu, mx0, 2));
        mx1 = fmaxf(mx1, __shfl_xor_sync(0xffffffffu, mx1, 1));
        mx1 = fmaxf(mx1, __shfl_xor_sync(0xffffffffu, mx1, 2));
        float mn0 = fmaxf(m0, mx0 * scale);
        float mn1 = fmaxf(m1, mx1 * scale);
        float c0 = __expf(m0 - mn0), c1 = __expf(m1 - mn1);
        l0 *= c0; l1 *= c1;

        u32 pah[4][4], pal[4][4];
        float sum0 = 0.f, sum1 = 0.f;
        #pragma unroll
        for (int t = 0; t < 8; t++) {
            float p0 = __expf(sacc[t][0]*scale - mn0);
            float p1 = __expf(sacc[t][1]*scale - mn0);
            float p2 = __expf(sacc[t][2]*scale - mn1);
            float p3 = __expf(sacc[t][3]*scale - mn1);
            sum0 += p0 + p1; sum1 += p2 + p3;
            // split P to hi/lo
            float h0 = __bfloat162float(__float2bfloat16(p0));
            float h1 = __bfloat162float(__float2bfloat16(p1));
            float h2 = __bfloat162float(__float2bfloat16(p2));
            float h3 = __bfloat162float(__float2bfloat16(p3));
            int kp = t >> 1, su = (t & 1) * 2;
            pah[kp][su + 0] = pack_bf2(h0, h1);
            pah[kp][su + 1] = pack_bf2(h2, h3);
            pal[kp][su + 0] = pack_bf2(p0 - h0, p1 - h1);
            pal[kp][su + 1] = pack_bf2(p2 - h2, p3 - h3);
        }
        sum0 += __shfl_xor_sync(0xffffffffu, sum0, 1);
        sum0 += __shfl_xor_sync(0xffffffffu, sum0, 2);
        sum1 += __shfl_xor_sync(0xffffffffu, sum1, 1);
        sum1 += __shfl_xor_sync(0xffffffffu, sum1, 2);
        l0 += sum0; l1 += sum1;
        m0 = mn0; m1 = mn1;

        #pragma unroll
        for (int n = 0; n < 4; n++) {
            oacc[n][0] *= c0; oacc[n][1] *= c0;
            oacc[n][2] *= c1; oacc[n][3] *= c1;
        }

        // ---- O += P @ V (3-term), 4 n-tiles of 8 dh, 4 k-steps of 16 keys ----
        #pragma unroll
        for (int kp = 0; kp < 4; kp++) {
            u32 vh[4][2], vl[4][2];
            #pragma unroll
            for (int d = 0; d < 2; d++) {
                u32 off = (u32)((kp*16 + rofs) * ATSTR + d*16 + cofs) * 2;
                // trans: row dim = keys(k): m0=b0 tile 2d, m1=b1 tile 2d, m2=b0 tile 2d+1, m3=b1 tile 2d+1
                ldsm4t(vh[2*d][0], vh[2*d][1], vh[2*d+1][0], vh[2*d+1][1], bb + 10240 + off);
                ldsm4t(vl[2*d][0], vl[2*d][1], vl[2*d+1][0], vl[2*d+1][1], bb + 15360 + off);
            }
            #pragma unroll
            for (int n = 0; n < 4; n++) {
                mma16816(oacc[n], pah[kp], vh[n]);
                mma16816(oacc[n], pah[kp], vl[n]);
                mma16816(oacc[n], pal[kp], vh[n]);
            }
        }
        __syncthreads();
        buf ^= 1;
    }

    // ---- epilogue: normalize + split-store ----
    float i0 = 1.f / l0, i1 = 1.f / l1;
    size_t ro0 = (size_t)(b*LQ + q0 + r    ) * 256 + h*32;
    size_t ro8 = (size_t)(b*LQ + q0 + r + 8) * 256 + h*32;
    #pragma unroll
    for (int n = 0; n < 4; n++) {
        int col = n*8 + q2;
        float f0 = oacc[n][0] * i0, f1 = oacc[n][1] * i0;
        float f2 = oacc[n][2] * i1, f3 = oacc[n][3] * i1;
        float h0 = __bfloat162float(__float2bfloat16(f0));
        float h1 = __bfloat162float(__float2bfloat16(f1));
        float h2 = __bfloat162float(__float2bfloat16(f2));
        float h3 = __bfloat162float(__float2bfloat16(f3));
        *(u32*)&Ohi[ro0 + col] = pack_bf2(f0, f1);
        *(u32*)&Olo[ro0 + col] = pack_bf2(f0 - h0, f1 - h1);
        *(u32*)&Ohi[ro8 + col] = pack_bf2(f2, f3);
        *(u32*)&Olo[ro8 + col] = pack_bf2(f2 - h2, f3 - h3);
    }
}

// ---------------- layernorm(a + b) * g + beta (optional split out) ----------------
template<int SPLIT>
__global__ __launch_bounds__(256) void ln_kernel_t(
    const float* __restrict__ a, const float* __restrict__ b,
    const float* __restrict__ g, const float* __restrict__ be,
    float* __restrict__ out,
    __nv_bfloat16* __restrict__ ohi, __nv_bfloat16* __restrict__ olo)
{
    __shared__ float red[8];
    int row = blockIdx.x, t = threadIdx.x;
    float x = a[(size_t)row*Dm + t] + b[(size_t)row*Dm + t];

    float s = x;
    #pragma unroll
    for (int o = 16; o; o >>= 1) s += __shfl_xor_sync(0xffffffffu, s, o);
    if ((t & 31) == 0) red[t >> 5] = s;
    __syncthreads();
    float tot = 0.f;
    #pragma unroll
    for (int i = 0; i < 8; i++) tot += red[i];
    float mean = tot * (1.f / Dm);
    float d0 = x - mean;
    __syncthreads();

    float sq = d0 * d0;
    #pragma unroll
    for (int o = 16; o; o >>= 1) sq += __shfl_xor_sync(0xffffffffu, sq, o);
    if ((t & 31) == 0) red[t >> 5] = sq;
    __syncthreads();
    float tot2 = 0.f;
    #pragma unroll
    for (int i = 0; i < 8; i++) tot2 += red[i];
    float var = tot2 * (1.f / Dm);

    float y = d0 * rsqrtf(var + EPSV) * g[t] + be[t];
    out[(size_t)row*Dm + t] = y;
    if (SPLIT) {
        __nv_bfloat16 h, lo_;
        split1(y, h, lo_);
        ohi[(size_t)row*Dm + t] = h;
        olo[(size_t)row*Dm + t] = lo_;
    }
}

// ---------------- deformable sampler (attw softmax fused, split out) ----------------
__global__ __launch_bounds__(256) void sampler_kernel(
    const float* __restrict__ refp,
    const float* __restrict__ off,
    const float* __restrict__ attw,
    const float* __restrict__ value,
    __nv_bfloat16* __restrict__ shi, __nv_bfloat16* __restrict__ slo)
{
    int bq = blockIdx.x;
    int b = bq >> 10;
    int t = threadIdx.x;
    int h = t >> 5, lane = t & 31;

    float logit = (lane < 16) ? attw[(size_t)bq*128 + h*16 + lane] : -1e30f;
    float mx = logit;
    #pragma unroll
    for (int o = 16; o; o >>= 1) mx = fmaxf(mx, __shfl_xor_sync(0xffffffffu, mx, o));
    float e = (lane < 16) ? __expf(logit - mx) : 0.f;
    float sum = e;
    #pragma unroll
    for (int o = 16; o; o >>= 1) sum += __shfl_xor_sync(0xffffffffu, sum, o);
    float aw_lane = e / sum;

    const int wls[4]    = {64, 32, 16, 8};
    const int hls[4]    = {64, 32, 16, 8};
    const int starts[4] = {0, 4096, 5120, 5376};

    const float* rp = refp + ((size_t)bq * Ll) * 2;
    float acc = 0.f;

    #pragma unroll
    for (int l = 0; l < Ll; l++) {
        int wl = wls[l], hl = hls[l], st = starts[l];
        float rx = rp[l*2 + 0];
        float ry = rp[l*2 + 1];
        #pragma unroll
        for (int p = 0; p < Pp; p++) {
            int n = (h*Ll + l)*Pp + p;
            float ox = off[(size_t)bq*256 + n*2 + 0];
            float oy = off[(size_t)bq*256 + n*2 + 1];
            float x = (rx + ox / (float)wl) * (float)wl - 0.5f;
            float y = (ry + oy / (float)hl) * (float)hl - 0.5f;
            float x0f = floorf(x), y0f = floorf(y);
            float lx = x - x0f, ly = y - y0f;
            int x0 = (int)x0f, y0 = (int)y0f;
            float aw = __shfl_sync(0xffffffffu, aw_lane, l*Pp + p);

            float g00 = 0.f, g01 = 0.f, g10 = 0.f, g11 = 0.f;
            if (x0   >= 0 && x0   < wl && y0   >= 0 && y0   < hl)
                g00 = value[((size_t)(b*LV + st + y0*wl + x0))*Dm + h*DH + lane];
            if (x0+1 >= 0 && x0+1 < wl && y0   >= 0 && y0   < hl)
                g01 = value[((size_t)(b*LV + st + y0*wl + x0+1))*Dm + h*DH + lane];
            if (x0   >= 0 && x0   < wl && y0+1 >= 0 && y0+1 < hl)
                g10 = value[((size_t)(b*LV + st + (y0+1)*wl + x0))*Dm + h*DH + lane];
            if (x0+1 >= 0 && x0+1 < wl && y0+1 >= 0 && y0+1 < hl)
                g11 = value[((size_t)(b*LV + st + (y0+1)*wl + x0+1))*Dm + h*DH + lane];

            float sv = g00*(1.f-lx)*(1.f-ly) + g01*lx*(1.f-ly)
                     + g10*(1.f-lx)*ly       + g11*lx*ly;
            acc += aw * sv;
        }
    }
    __nv_bfloat16 hh, ll;
    split1(acc, hh, ll);
    shi[(size_t)bq*Dm + h*DH + lane] = hh;
    slo[(size_t)bq*Dm + h*DH + lane] = ll;
}

// ---------------- launch ----------------
extern "C" void kernel_launch(void* const* d_in, const int* in_sizes, int n_in,
                              void* d_out, int out_size) {
    const float* tgt  = (const float*)d_in[0];
    const float* qpos = (const float*)d_in[1];
    const float* refp = (const float*)d_in[2];
    const float* src  = (const float*)d_in[3];
    const float* in_w = (const float*)d_in[4];
    const float* in_b = (const float*)d_in[5];
    const float* ow   = (const float*)d_in[6];
    const float* ob   = (const float*)d_in[7];
    const float* n2g  = (const float*)d_in[8];
    const float* n2b  = (const float*)d_in[9];
    const float* vw   = (const float*)d_in[10];
    const float* vb   = (const float*)d_in[11];
    const float* offw = (const float*)d_in[12];
    const float* offb = (const float*)d_in[13];
    const float* aww  = (const float*)d_in[14];
    const float* awb  = (const float*)d_in[15];
    const float* opw  = (const float*)d_in[16];
    const float* opb  = (const float*)d_in[17];
    const float* n1g  = (const float*)d_in[18];
    const float* n1b  = (const float*)d_in[19];
    const float* l1w  = (const float*)d_in[20];
    const float* l1b  = (const float*)d_in[21];
    const float* l2w  = (const float*)d_in[22];
    const float* l2b  = (const float*)d_in[23];
    const float* n3g  = (const float*)d_in[24];
    const float* n3b  = (const float*)d_in[25];
    float* out = (float*)d_out;

    float *p_tmp, *p_tgt, *p_tgt2, *p_value, *p_off, *p_attw;
    __nv_bfloat16 *p_ahi, *p_alo, *p_bhi, *p_blo, *p_vhi, *p_vlo, *p_whi, *p_wlo;
    cudaGetSymbolAddress((void**)&p_tmp,  g_tmp);
    cudaGetSymbolAddress((void**)&p_tgt,  g_tgt);
    cudaGetSymbolAddress((void**)&p_tgt2, g_tgt2);
    cudaGetSymbolAddress((void**)&p_value,g_value);
    cudaGetSymbolAddress((void**)&p_off,  g_off);
    cudaGetSymbolAddress((void**)&p_attw, g_attw);
    cudaGetSymbolAddress((void**)&p_ahi,  g_ahi);
    cudaGetSymbolAddress((void**)&p_alo,  g_alo);
    cudaGetSymbolAddress((void**)&p_bhi,  g_bhi);
    cudaGetSymbolAddress((void**)&p_blo,  g_blo);
    cudaGetSymbolAddress((void**)&p_vhi,  g_vhi);
    cudaGetSymbolAddress((void**)&p_vlo,  g_vlo);
    cudaGetSymbolAddress((void**)&p_whi,  g_whi);
    cudaGetSymbolAddress((void**)&p_wlo,  g_wlo);

    cudaFuncSetAttribute(mma_gemm, cudaFuncAttributeMaxDynamicSharedMemorySize, SMT);

    const int n4 = M1 * Dm / 4;

    // ---- weight splits ----
    #define SPL(src_, off_, n_) split_kernel<<<((n_)/4 + 255)/256, 256>>>(src_, p_whi + (off_), p_wlo + (off_), (n_)/4)
    SPL(in_w, WO_IN,  768*256);
    SPL(ow,   WO_OW,  65536);
    SPL(vw,   WO_VW,  65536);
    SPL(offw, WO_OFF, 65536);
    SPL(aww,  WO_AW,  32768);
    SPL(opw,  WO_OP,  65536);
    SPL(l1w,  WO_L1,  262144);
    SPL(l2w,  WO_L2,  262144);
    #undef SPL

    // 1. q = tgt + qpos -> bf16 split
    add_split_kernel<<<(n4 + 255)/256, 256>>>(tgt, qpos, p_ahi, p_alo, n4);
    // 2. [Q|K] = q @ in_w[0:512].T + b  -> split bf16 (g_bhi/g_blo)
    mma_gemm<<<dim3(8, M1/128), 256, SMT>>>(p_ahi, p_alo, p_whi + WO_IN, p_wlo + WO_IN, in_b, 0, p_bhi, p_blo, 256, 512, 0, 1);
    // 3. V = tgt @ in_w[512:768].T + b  -> split bf16 (g_vhi/g_vlo)
    split_kernel<<<(n4 + 255)/256, 256>>>(tgt, p_ahi, p_alo, n4);
    mma_gemm<<<dim3(4, M1/128), 256, SMT>>>(p_ahi, p_alo, p_whi + WO_INV, p_wlo + WO_INV, in_b + 512, 0, p_vhi, p_vlo, 256, 256, 0, 1);
    // 4. HMMA flash attention (writes split att to g_ahi/g_alo)
    attn_mma<<<dim3(LQ/64, Bq*Hh), 128>>>(p_bhi, p_blo, p_vhi, p_vlo, p_ahi, p_alo);
    // 5. out_proj
    mma_gemm<<<dim3(4, M1/128), 256, SMT>>>(p_ahi, p_alo, p_whi + WO_OW, p_wlo + WO_OW, ob, p_tmp, 0, 0, 256, 256, 0, 0);
    // 6. tgt = LN(tgt + tgt2, norm2)
    ln_kernel_t<0><<<M1, 256>>>(tgt, p_tmp, n2g, n2b, p_tgt, 0, 0);
    // 7. q2 = tgt + qpos -> off + attw projections
    add_split_kernel<<<(n4 + 255)/256, 256>>>(p_tgt, qpos, p_ahi, p_alo, n4);
    mma_gemm<<<dim3(4, M1/128), 256, SMT>>>(p_ahi, p_alo, p_whi + WO_OFF, p_wlo + WO_OFF, offb, p_off, 0, 0, 256, 256, 0, 0);
    mma_gemm<<<dim3(2, M1/128), 256, SMT>>>(p_ahi, p_alo, p_whi + WO_AW, p_wlo + WO_AW, awb, p_attw, 0, 0, 256, 128, 0, 0);
    // 8. value = src @ value_w.T + b
    split_kernel<<<((int)(MV*(size_t)Dm/4) + 255)/256, 256>>>(src, p_ahi, p_alo, (int)(MV*(size_t)Dm/4));
    mma_gemm<<<dim3(4, MV/128), 256, SMT>>>(p_ahi, p_alo, p_whi + WO_VW, p_wlo + WO_VW, vb, p_value, 0, 0, 256, 256, 0, 0);
    // 9. sampler (writes split samp directly)
    sampler_kernel<<<M1, 256>>>(refp, p_off, p_attw, p_value, p_ahi, p_alo);
    // 10. outp proj
    mma_gemm<<<dim3(4, M1/128), 256, SMT>>>(p_ahi, p_alo, p_whi + WO_OP, p_wlo + WO_OP, opb, p_tmp, 0, 0, 256, 256, 0, 0);
    // 11. tgt2 = LN(tgt + t, norm1) -> fp32 + split
    ln_kernel_t<1><<<M1, 256>>>(p_tgt, p_tmp, n1g, n1b, p_tgt2, p_ahi, p_alo);
    // 12. ffn mid = relu(tgt2 @ l1w.T + b) -> split output
    mma_gemm<<<dim3(16, M1/128), 256, SMT>>>(p_ahi, p_alo, p_whi + WO_L1, p_wlo + WO_L1, l1b, 0, p_bhi, p_blo, 256, 1024, 1, 1);
    // 13. ffn out
    mma_gemm<<<dim3(4, M1/128), 256, SMT>>>(p_bhi, p_blo, p_whi + WO_L2, p_wlo + WO_L2, l2b, p_tmp, 0, 0, 1024, 256, 0, 0);
    // 14. out = LN(tgt2 + t2, norm3)
    ln_kernel_t<0><<<M1, 256>>>(p_tgt2, p_tmp, n3g, n3b, out, 0, 0);
}